// round 14
// baseline (speedup 1.0000x reference)
#include <cuda_runtime.h>
#include <cuda_fp16.h>
#include <math.h>
#include <stdint.h>

#define BB   64
#define TT   351
#define DD   512
#define HH   8
#define DFFX 1024
#define BT   (BB*TT)       // 22464
#define MP   22528
#define HPR  22784
#define TP   384
#define ZZ   (BB*HH)       // 512
#define ZT64 ((size_t)ZZ*TP*64)
#define STAGE_BYTES 36864
#define SMEMSZ (3*STAGE_BYTES)

// fused-attention smem layout (bytes), q-block = 48 rows
#define FS_PITCH 392
#define AT_QU 75264
#define AT_QV 84480
#define AT_B0 93696
#define AT_B1 102912
#define AF_A  75264
#define AF_PITCH 784
#define FS_TOT 112896             // occ 2

// ---------------- scratch ------------------------------------------------------------
static __device__ __half g_quh[ZT64];
static __device__ __half g_qvh[ZT64];
static __device__ __half g_kkh[ZT64];
static __device__ __half g_pph[3*ZT64];
static __device__ __half g_vth[ZT64];
static __device__ __half g_xnh[MP*(size_t)DD];
static __device__ __half g_mkh[MP*(size_t)DD];
static __device__ __half g_cxh[MP*(size_t)DD];
static __device__ __half g_hph[(size_t)HPR*DFFX];
static __device__ __half g_wqkv[3*3*DD*DD];
static __device__ __half g_wph[3*DD*DD], g_woh[3*DD*DD];
static __device__ __half g_w1h[3*DFFX*DD];
static __device__ __half g_w2h[3*3*DD*DFFX];

// ---------------- PTX helpers --------------------------------------------------------
__device__ __forceinline__ uint32_t smem_u32(const void* p) {
    uint32_t a;
    asm("{ .reg .u64 t; cvta.to.shared.u64 t, %1; cvt.u32.u64 %0, t; }" : "=r"(a) : "l"(p));
    return a;
}
__device__ __forceinline__ void cp16(uint32_t dst, const void* src) {
    asm volatile("cp.async.cg.shared.global [%0], [%1], 16;" :: "r"(dst), "l"(src) : "memory");
}
#define CP_COMMIT() asm volatile("cp.async.commit_group;" ::: "memory")
#define CP_WAIT2()  asm volatile("cp.async.wait_group 2;" ::: "memory")
#define CP_WAIT1()  asm volatile("cp.async.wait_group 1;" ::: "memory")
#define CP_WAIT0()  asm volatile("cp.async.wait_group 0;" ::: "memory")

__device__ __forceinline__ void mma16816(float* c, const uint32_t* a, const uint32_t* b) {
    asm volatile(
        "mma.sync.aligned.m16n8k16.row.col.f32.f16.f16.f32 "
        "{%0,%1,%2,%3}, {%4,%5,%6,%7}, {%8,%9}, {%0,%1,%2,%3};"
        : "+f"(c[0]), "+f"(c[1]), "+f"(c[2]), "+f"(c[3])
        : "r"(a[0]), "r"(a[1]), "r"(a[2]), "r"(a[3]), "r"(b[0]), "r"(b[1]));
}
__device__ __forceinline__ void ldsm4(uint32_t* r, uint32_t addr) {
    asm volatile("ldmatrix.sync.aligned.m8n8.x4.shared.b16 {%0,%1,%2,%3}, [%4];"
        : "=r"(r[0]), "=r"(r[1]), "=r"(r[2]), "=r"(r[3]) : "r"(addr));
}
__device__ __forceinline__ uint32_t packh(float a, float b) {
    __half2 h = __floats2half2_rn(a, b);
    return *reinterpret_cast<uint32_t*>(&h);
}

// ---------------- conversion kernels -------------------------------------------------
__global__ void cvt_qkv(const float* __restrict__ Wq, const float* __restrict__ Wk,
                        const float* __restrict__ Wv, __half* __restrict__ dst, int n4per) {
    int i = blockIdx.x * 256 + threadIdx.x;
    if (i >= n4per) return;
    int tsel = blockIdx.y;
    const float* s = (tsel == 0) ? Wq : (tsel == 1) ? Wk : Wv;
    float4 v = ((const float4*)s)[i];
    const int per_l4 = DD * DD / 4;
    int l = i / per_l4, r = i - l * per_l4;
    long di = (long)l * (3 * per_l4) + (long)tsel * per_l4 + r;
    uint2 st; st.x = packh(v.x, v.y); st.y = packh(v.z, v.w);
    ((uint2*)dst)[di] = st;
}
// segmented: y=0 Wp, y=1 Wo, y=2 W1, y=3 MSK (different lengths, guarded)
struct CvtSeg { const float* src; __half* dst; int n4; };
__global__ void cvt_misc(CvtSeg s0, CvtSeg s1, CvtSeg s2, CvtSeg s3) {
    CvtSeg s = (blockIdx.y == 0) ? s0 : (blockIdx.y == 1) ? s1 : (blockIdx.y == 2) ? s2 : s3;
    int i = blockIdx.x * 256 + threadIdx.x;
    if (i >= s.n4) return;
    float4 v = ((const float4*)s.src)[i];
    uint2 st; st.x = packh(v.x, v.y); st.y = packh(v.z, v.w);
    ((uint2*)s.dst)[i] = st;
}
// W2 in: [l][n][k][s] -> out [l][s][n][k]
__global__ void cvt_w2(const float* __restrict__ in, __half* __restrict__ hi) {
    int idx = blockIdx.x * 256 + threadIdx.x;
    const int per_l = 3 * DD * DFFX;
    if (idx >= 3 * per_l) return;
    int l = idx / per_l; int r = idx - l * per_l;
    int s = r / (DD * DFFX); int r2 = r - s * (DD * DFFX);
    int n = r2 / DFFX; int k2 = r2 - n * DFFX;
    hi[idx] = __float2half_rn(in[(((size_t)l * DD + n) * DFFX + k2) * 3 + s]);
}

// ---------------- HMMA 1-term fp16 GEMM, K-chunk 64, 3-stage pipeline ----------------
// MODE 0: fp32 C (+ACC). MODE 1: fp16 padded-H remap (FF1). MODE 3: head-major
//         (supports gridDim.z layer batching). MODE 5: merged QKV epilogue.
template<int TAPS, bool ACC, bool RELU, int MODE>
__global__ __launch_bounds__(256, 2)
void hmma_gemm(const __half* __restrict__ Ahi, const __half* __restrict__ Bhi,
               const float* __restrict__ bias, const float* __restrict__ bias2,
               const float* __restrict__ bias3, const float* __restrict__ bias4,
               const float* __restrict__ bias5,
               float* __restrict__ Cf,
               __half* __restrict__ O1h, __half* __restrict__ O2h,
               __half* __restrict__ O3h, __half* __restrict__ O4h,
               int Mstore, int N, int K, long lws, long los) {
    extern __shared__ char sm[];
    uint32_t dbase = smem_u32(sm);
    Bhi += (long)blockIdx.z * lws;
    O1h += (long)blockIdx.z * los;
    int tid = threadIdx.x, lane = tid & 31, w = tid >> 5;
    int wm = (w & 1) << 6, wn = (w >> 1) << 5;
    int bm = blockIdx.y << 7, bn = blockIdx.x << 7;

    uint32_t so[4]; long ga[4], gb[4];
#pragma unroll
    for (int j = 0; j < 4; j++) {
        int idx = tid + 256 * j; int row = idx >> 3, c16 = idx & 7;
        so[j] = row * 144 + c16 * 16;
        int grow = bm + row;
        long arow;
        if (TAPS == 3) { int b = grow / 351; int t = grow - b * 351; arow = (long)b * 353 + t; }
        else arow = grow;
        ga[j] = arow * (long)K + c16 * 8;
        gb[j] = (long)(bn + row) * K + c16 * 8;
    }
    const int kch = K >> 6;
    const int nch = TAPS * kch;

#define LOAD_CHUNK(c, stg) do { \
        int s_ = (c) / kch; int kb_ = ((c) - s_ * kch) << 6; \
        long sK_ = (TAPS == 3) ? (long)s_ * K : 0; \
        long sNK_ = (TAPS == 3) ? (long)s_ * N * K : 0; \
        uint32_t sb_ = dbase + (stg) * STAGE_BYTES; \
        _Pragma("unroll") \
        for (int j = 0; j < 4; j++) { \
            cp16(sb_ + so[j],         Ahi + sK_ + ga[j] + kb_); \
            cp16(sb_ + 18432 + so[j], Bhi + sNK_ + gb[j] + kb_); \
        } \
    } while (0)

    float acc[4][4][4];
#pragma unroll
    for (int a = 0; a < 4; a++)
#pragma unroll
        for (int b = 0; b < 4; b++)
#pragma unroll
            for (int q2 = 0; q2 < 4; q2++) acc[a][b][q2] = 0.0f;

    int bq = lane & 3, bg = lane >> 2;
    uint32_t aoff = (uint32_t)(wm + (lane & 15)) * 144 + (uint32_t)(((lane >> 4) & 1) << 4);
    uint32_t boff = 18432u + (uint32_t)(wn + ((lane >> 4) << 3) + (lane & 7)) * 144
                  + (uint32_t)(((lane >> 3) & 1) << 4);

    LOAD_CHUNK(0, 0);
    CP_COMMIT();
    LOAD_CHUNK(1, 1);
    CP_COMMIT();
#pragma unroll 1
    for (int c = 0; c < nch; c++) {
        if (c + 2 < nch) LOAD_CHUNK(c + 2, (c + 2) % 3);
        CP_COMMIT();
        CP_WAIT2();
        __syncthreads();
        uint32_t sb = dbase + (c % 3) * STAGE_BYTES;
#pragma unroll
        for (int k16 = 0; k16 < 4; k16++) {
            uint32_t kof = k16 * 32;
            uint32_t bh[4][2], t[4];
            ldsm4(t, sb + boff + kof);
            bh[0][0] = t[0]; bh[0][1] = t[1]; bh[1][0] = t[2]; bh[1][1] = t[3];
            ldsm4(t, sb + boff + 2304 + kof);
            bh[2][0] = t[0]; bh[2][1] = t[1]; bh[3][0] = t[2]; bh[3][1] = t[3];
#pragma unroll
            for (int mi = 0; mi < 4; mi++) {
                uint32_t ah[4];
                ldsm4(ah, sb + aoff + mi * 2304 + kof);
#pragma unroll
                for (int ni = 0; ni < 4; ni++)
                    mma16816(acc[mi][ni], ah, bh[ni]);
            }
        }
        __syncthreads();
    }
#undef LOAD_CHUNK

#pragma unroll
    for (int mi = 0; mi < 4; mi++) {
#pragma unroll
        for (int half = 0; half < 2; half++) {
            int m = bm + wm + mi * 16 + bg + half * 8;
            if (m >= Mstore) continue;
            int b = 0, t = 0; long crow = m;
            if (MODE == 1) { b = m / 351; t = m - b * 351; crow = (long)b * 353 + 1 + t; }
            if (MODE >= 2) { b = m / 351; t = m - b * 351; }
#pragma unroll
            for (int ni = 0; ni < 4; ni++) {
                int col = bn + wn + ni * 8 + bq * 2;
                float v0 = acc[mi][ni][half * 2 + 0];
                float v1 = acc[mi][ni][half * 2 + 1];
                if (MODE == 0 || MODE == 1 || MODE == 3) {
                    if (bias) { v0 += bias[col]; v1 += bias[col + 1]; }
                }
                if (RELU) { v0 = fmaxf(v0, 0.0f); v1 = fmaxf(v1, 0.0f); }
                if (MODE == 0) {
                    float* cp = Cf + (long)m * N + col;
                    if (ACC) { v0 += cp[0]; v1 += cp[1]; }
                    float2 st; st.x = v0; st.y = v1;
                    *(float2*)cp = st;
                } else if (MODE == 1) {
                    *(uint32_t*)(O1h + crow * (long)N + col) = packh(v0, v1);
                } else if (MODE == 3) {
                    int h = col >> 6, d = col & 63;
                    long base = ((long)(b * 8 + h) * TP + t) * 64 + d;
                    *(uint32_t*)(O1h + base) = packh(v0, v1);
                } else if (MODE == 5) {
                    int seg = col >> 9, cs = col & 511;
                    int h = cs >> 6, d = cs & 63;
                    if (seg == 0) {
                        long base = ((long)(b * 8 + h) * TP + t) * 64 + d;
                        float q0v = v0 + bias[cs], q1v = v1 + bias[cs + 1];
                        *(uint32_t*)(O1h + base) = packh(q0v + bias2[cs], q1v + bias2[cs + 1]);
                        *(uint32_t*)(O2h + base) = packh(q0v + bias3[cs], q1v + bias3[cs + 1]);
                    } else if (seg == 1) {
                        long base = ((long)(b * 8 + h) * TP + t) * 64 + d;
                        *(uint32_t*)(O3h + base) = packh(v0 + bias4[cs], v1 + bias4[cs + 1]);
                    } else {
                        float u0 = v0 + bias5[cs], u1 = v1 + bias5[cs + 1];
                        O4h[((long)(b * 8 + h) * 64 + d) * TP + t]     = __float2half_rn(u0);
                        O4h[((long)(b * 8 + h) * 64 + d + 1) * TP + t] = __float2half_rn(u1);
                    }
                }
            }
        }
    }
}

// ---------------- fully fused attention ----------------------------------------------
__global__ __launch_bounds__(256, 2)
void attn_fused(const __half* __restrict__ quh, const __half* __restrict__ qvh,
                const __half* __restrict__ kkh, const __half* __restrict__ pph,
                const __half* __restrict__ vth, __half* __restrict__ Ch) {
    extern __shared__ char sm[];
    uint32_t dbase = smem_u32(sm);
    float* S = (float*)sm;
    int z = blockIdx.y, q0 = blockIdx.x * 48;
    int tid = threadIdx.x, lane = tid & 31, w = tid >> 5;
    int cb = w << 3;
    int bq = lane & 3, bg = lane >> 2;

    for (int i = tid; i < 512; i += 256) {
        int r = i >> 3, c = i & 7;
        int gq = q0 + r; if (gq >= TP) gq = q0;
        cp16(dbase + AT_QU + r * 144 + c * 16, quh + ((long)z * TP + gq) * 64 + c * 8);
        cp16(dbase + AT_QV + r * 144 + c * 16, qvh + ((long)z * TP + gq) * 64 + c * 8);
        cp16(dbase + AT_B0 + r * 144 + c * 16, kkh + ((long)z * TP + r) * 64 + c * 8);
    }
    CP_COMMIT();
    CP_WAIT0();
    __syncthreads();

    uint32_t afr[4][4][4];
#pragma unroll
    for (int mi = 0; mi < 3; mi++)
#pragma unroll
        for (int k16 = 0; k16 < 4; k16++) {
            const char* pa = sm + AT_QU + (mi * 16 + bg) * 144 + k16 * 32 + bq * 4;
            afr[mi][k16][0] = *(const uint32_t*)pa;
            afr[mi][k16][1] = *(const uint32_t*)(pa + 8 * 144);
            afr[mi][k16][2] = *(const uint32_t*)(pa + 16);
            afr[mi][k16][3] = *(const uint32_t*)(pa + 8 * 144 + 16);
        }

#pragma unroll 1
    for (int ch = 0; ch < 12; ch++) {
        if (ch + 1 < 12) {
            const __half* src = (ch + 1 < 6) ? kkh : pph;
            int rows0 = ((ch + 1) % 6) * 64;
            uint32_t bb = ((ch + 1) & 1) ? AT_B1 : AT_B0;
            for (int i = tid; i < 512; i += 256) {
                int r = i >> 3, c = i & 7;
                cp16(dbase + bb + r * 144 + c * 16,
                     src + ((long)z * TP + rows0 + r) * 64 + c * 8);
            }
        }
        CP_COMMIT();
        CP_WAIT1();
        __syncthreads();
        if (ch == 6) {
#pragma unroll
            for (int mi = 0; mi < 4; mi++)
#pragma unroll
                for (int k16 = 0; k16 < 4; k16++) {
                    const char* pa = sm + AT_QV + (mi * 16 + bg) * 144 + k16 * 32 + bq * 4;
                    afr[mi][k16][0] = *(const uint32_t*)pa;
                    afr[mi][k16][1] = *(const uint32_t*)(pa + 8 * 144);
                    afr[mi][k16][2] = *(const uint32_t*)(pa + 16);
                    afr[mi][k16][3] = *(const uint32_t*)(pa + 8 * 144 + 16);
                }
        }
        uint32_t bb = (ch & 1) ? AT_B1 : AT_B0;
        int col0 = (ch % 6) * 64;
        if (ch < 6) {
            float acc[3][4];
#pragma unroll
            for (int a = 0; a < 3; a++)
#pragma unroll
                for (int e = 0; e < 4; e++) acc[a][e] = 0.0f;
#pragma unroll
            for (int k16 = 0; k16 < 4; k16++) {
                const char* pb = sm + bb + (cb + bg) * 144 + k16 * 32 + bq * 4;
                uint32_t bh[2];
                bh[0] = *(const uint32_t*)pb;
                bh[1] = *(const uint32_t*)(pb + 16);
#pragma unroll
                for (int mi = 0; mi < 3; mi++)
                    mma16816(acc[mi], afr[mi][k16], bh);
            }
#pragma unroll
            for (int mi = 0; mi < 3; mi++)
#pragma unroll
                for (int half = 0; half < 2; half++) {
                    int r = mi * 16 + bg + half * 8;
                    int col = col0 + cb + bq * 2;
                    S[r * FS_PITCH + col]     = acc[mi][half * 2 + 0];
                    S[r * FS_PITCH + col + 1] = acc[mi][half * 2 + 1];
                }
        } else {
            float acc[4][4];
#pragma unroll
            for (int a = 0; a < 4; a++)
#pragma unroll
                for (int e = 0; e < 4; e++) acc[a][e] = 0.0f;
#pragma unroll
            for (int k16 = 0; k16 < 4; k16++) {
                const char* pb = sm + bb + (cb + bg) * 144 + k16 * 32 + bq * 4;
                uint32_t bh[2];
                bh[0] = *(const uint32_t*)pb;
                bh[1] = *(const uint32_t*)(pb + 16);
#pragma unroll
                for (int mi = 0; mi < 4; mi++)
                    mma16816(acc[mi], afr[mi][k16], bh);
            }
#pragma unroll
            for (int mi = 0; mi < 4; mi++)
#pragma unroll
                for (int half = 0; half < 2; half++) {
                    int r = mi * 16 + bg + half * 8;
                    if (r > 48) continue;
                    int rp = q0 + r;
#pragma unroll
                    for (int e = 0; e < 2; e++) {
                        int jj = col0 + cb + bq * 2 + e;
                        if (jj >= TT) continue;
                        float v = acc[mi][half * 2 + e];
                        if (jj >= 350 - rp) {
                            if (r < 48) S[r * FS_PITCH + jj - 350 + rp] += v;
                        } else if (r >= 1) {
                            S[(r - 1) * FS_PITCH + jj + rp + 1] += v;
                        }
                    }
                }
        }
        __syncthreads();
    }

    // ---- softmax via ex2.approx.f16x2 -> fp16 A tile (fully convergent) ----
    if (tid < 192) {
        int r = tid >> 2, qu = tid & 3;
        const float scale = 0.044194173824159216f;
        const float a_l2 = scale * 1.4426950408889634f;
        float* Srow = S + r * FS_PITCH;
        char* Arow = sm + AF_A + r * AF_PITCH;
        int c0 = qu * 96;
        float mx = -1e30f;
        for (int cc = c0; cc < c0 + 96; cc++)
            if (cc < TT) mx = fmaxf(mx, Srow[cc]);
        mx = fmaxf(mx, __shfl_xor_sync(0xffffffffu, mx, 1));
        mx = fmaxf(mx, __shfl_xor_sync(0xffffffffu, mx, 2));
        float boff2 = -mx * a_l2;
        float sum = 0.0f;
        for (int cc = c0; cc < c0 + 96; cc += 2) {
            float x0 = (cc < TT)     ? Srow[cc]     * a_l2 + boff2 : -60.0f;
            float x1 = (cc + 1 < TT) ? Srow[cc + 1] * a_l2 + boff2 : -60.0f;
            __half2 hx = __floats2half2_rn(x0, x1);
            __half2 he = h2exp2(hx);
            float2 fe = __half22float2(he);
            sum += fe.x + fe.y;
            *(__half2*)(Arow + cc * 2) = he;
        }
        sum += __shfl_xor_sync(0xffffffffu, sum, 1);
        sum += __shfl_xor_sync(0xffffffffu, sum, 2);
        __half2 inv2 = __half2half2(__float2half_rn(1.0f / sum));
        for (int cc = c0; cc < c0 + 96; cc += 2) {
            __half2 v = *(__half2*)(Arow + cc * 2);
            *(__half2*)(Arow + cc * 2) = __hmul2(v, inv2);
        }
    }
    __syncthreads();

    // ---- load V tile over dead score region ----
    for (int i = tid; i < 3072; i += 256) {
        int d = i / 48, c16 = i - d * 48;
        cp16(dbase + d * AF_PITCH + c16 * 16,
             vth + ((long)z * 64 + d) * TP + c16 * 8);
    }
    CP_COMMIT(); CP_WAIT0(); __syncthreads();

    // ---- ctx GEMM: out[48 x 64] = A[48 x 384] @ V^T, 6 warps, ldsm fragments ----
    if (w < 6) {
        int wr = w % 3, wc = w / 3;
        uint32_t aoffc = smem_u32(sm) + AF_A
                       + (uint32_t)(wr * 16 + (lane & 15)) * AF_PITCH
                       + (uint32_t)(((lane >> 4) & 1) << 4);
        uint32_t boffc = smem_u32(sm)
                       + (uint32_t)(wc * 32 + ((lane >> 4) << 3) + (lane & 7)) * AF_PITCH
                       + (uint32_t)(((lane >> 3) & 1) << 4);
        float acc[4][4];
#pragma unroll
        for (int a = 0; a < 4; a++)
#pragma unroll
            for (int e = 0; e < 4; e++) acc[a][e] = 0.0f;
#pragma unroll 1
        for (int k16 = 0; k16 < 24; k16++) {
            uint32_t kof = k16 * 32;
            uint32_t ah[4], t[4], bh[4][2];
            ldsm4(ah, aoffc + kof);
            ldsm4(t, boffc + kof);
            bh[0][0] = t[0]; bh[0][1] = t[1]; bh[1][0] = t[2]; bh[1][1] = t[3];
            ldsm4(t, boffc + 16 * AF_PITCH + kof);
            bh[2][0] = t[0]; bh[2][1] = t[1]; bh[3][0] = t[2]; bh[3][1] = t[3];
#pragma unroll
            for (int ni = 0; ni < 4; ni++)
                mma16816(acc[ni], ah, bh[ni]);
        }
        int b = z >> 3, h = z & 7;
#pragma unroll
        for (int half = 0; half < 2; half++) {
            int gq = q0 + wr * 16 + bg + half * 8;
            if (gq >= TT) continue;
#pragma unroll
            for (int ni = 0; ni < 4; ni++) {
                int col = wc * 32 + ni * 8 + bq * 2;
                long addr = ((long)(b * 351 + gq)) * DD + h * 64 + col;
                *(uint32_t*)(Ch + addr) = packh(acc[ni][half * 2], acc[ni][half * 2 + 1]);
            }
        }
    }
}

// ---------------- add pos-emb + LayerNorm (float4-vectorized) ------------------------
template<bool F16O>
__global__ void addln_kernel(const float* __restrict__ xin, float* __restrict__ xupd,
                             const float* __restrict__ pe,
                             const float* __restrict__ ga, const float* __restrict__ gb,
                             float* __restrict__ out, __half* __restrict__ ohi) {
    int row = blockIdx.x;
    int t   = row % TT;
    int tid = threadIdx.x;
    int c4 = tid << 2;
    float4 v4 = *(const float4*)(xin + (size_t)row * DD + c4);
    if (pe) {
        float4 p4 = *(const float4*)(pe + (size_t)t * DD + c4);
        v4.x += p4.x; v4.y += p4.y; v4.z += p4.z; v4.w += p4.w;
        *(float4*)(xupd + (size_t)row * DD + c4) = v4;
    }
    __shared__ float sh[4];
    float s = v4.x + v4.y + v4.z + v4.w;
#pragma unroll
    for (int o = 16; o > 0; o >>= 1) s += __shfl_xor_sync(0xffffffffu, s, o);
    if ((tid & 31) == 0) sh[tid >> 5] = s;
    __syncthreads();
    float mean = (sh[0] + sh[1] + sh[2] + sh[3]) * (1.0f / DD);
    __syncthreads();
    float d0 = v4.x - mean, d1 = v4.y - mean, d2 = v4.z - mean, d3 = v4.w - mean;
    float sq = d0 * d0 + d1 * d1 + d2 * d2 + d3 * d3;
#pragma unroll
    for (int o = 16; o > 0; o >>= 1) sq += __shfl_xor_sync(0xffffffffu, sq, o);
    if ((tid & 31) == 0) sh[tid >> 5] = sq;
    __syncthreads();
    float var  = sh[0] + sh[1] + sh[2] + sh[3];
    float stdv = sqrtf(var * (1.0f / (DD - 1)));
    float inv  = 1.0f / (stdv + 1e-6f);
    float4 a4 = *(const float4*)(ga + c4);
    float4 b4 = *(const float4*)(gb + c4);
    float o0 = a4.x * d0 * inv + b4.x;
    float o1 = a4.y * d1 * inv + b4.y;
    float o2 = a4.z * d2 * inv + b4.z;
    float o3 = a4.w * d3 * inv + b4.w;
    if (F16O) {
        uint2 st; st.x = packh(o0, o1); st.y = packh(o2, o3);
        *(uint2*)(ohi + (size_t)row * DD + c4) = st;
    } else {
        float4 st; st.x = o0; st.y = o1; st.z = o2; st.w = o3;
        *(float4*)(out + (size_t)row * DD + c4) = st;
    }
}

// ------------------------------------ launch -----------------------------------------
extern "C" void kernel_launch(void* const* d_in, const int* in_sizes, int n_in,
                              void* d_out, int out_size) {
    const float* X0  = (const float*)d_in[0];
    const float* MSK = (const float*)d_in[1];
    const float* PE  = (const float*)d_in[2];
    const float* Wq  = (const float*)d_in[3];
    const float* bq  = (const float*)d_in[4];
    const float* Wk  = (const float*)d_in[5];
    const float* bk  = (const float*)d_in[6];
    const float* Wv  = (const float*)d_in[7];
    const float* bv  = (const float*)d_in[8];
    const float* Wp  = (const float*)d_in[9];
    const float* Ub  = (const float*)d_in[10];
    const float* Vb  = (const float*)d_in[11];
    const float* Wo  = (const float*)d_in[12];
    const float* bo  = (const float*)d_in[13];
    const float* l1a = (const float*)d_in[14];
    const float* l1b = (const float*)d_in[15];
    const float* l2a = (const float*)d_in[16];
    const float* l2b = (const float*)d_in[17];
    const float* W1  = (const float*)d_in[18];
    const float* b1  = (const float*)d_in[19];
    const float* W2  = (const float*)d_in[20];
    const float* b2  = (const float*)d_in[21];
    const float* fna = (const float*)d_in[22];
    const float* fnb = (const float*)d_in[23];
    float* x = (float*)d_out;

    __half *quh, *qvh, *kkh, *pph, *vth;
    __half *xnh, *mkh, *cxh, *hph;
    __half *wqkv, *wph, *woh, *w1h, *w2h;
    cudaGetSymbolAddress((void**)&quh, g_quh); cudaGetSymbolAddress((void**)&qvh, g_qvh);
    cudaGetSymbolAddress((void**)&kkh, g_kkh); cudaGetSymbolAddress((void**)&pph, g_pph);
    cudaGetSymbolAddress((void**)&vth, g_vth);
    cudaGetSymbolAddress((void**)&xnh, g_xnh); cudaGetSymbolAddress((void**)&mkh, g_mkh);
    cudaGetSymbolAddress((void**)&cxh, g_cxh); cudaGetSymbolAddress((void**)&hph, g_hph);
    cudaGetSymbolAddress((void**)&wqkv, g_wqkv);
    cudaGetSymbolAddress((void**)&wph, g_wph); cudaGetSymbolAddress((void**)&woh, g_woh);
    cudaGetSymbolAddress((void**)&w1h, g_w1h); cudaGetSymbolAddress((void**)&w2h, g_w2h);

    cudaFuncSetAttribute(hmma_gemm<1, true,  false, 0>, cudaFuncAttributeMaxDynamicSharedMemorySize, SMEMSZ);
    cudaFuncSetAttribute(hmma_gemm<3, true,  false, 0>, cudaFuncAttributeMaxDynamicSharedMemorySize, SMEMSZ);
    cudaFuncSetAttribute(hmma_gemm<1, false, true,  1>, cudaFuncAttributeMaxDynamicSharedMemorySize, SMEMSZ);
    cudaFuncSetAttribute(hmma_gemm<1, false, false, 3>, cudaFuncAttributeMaxDynamicSharedMemorySize, SMEMSZ);
    cudaFuncSetAttribute(hmma_gemm<1, false, false, 5>, cudaFuncAttributeMaxDynamicSharedMemorySize, SMEMSZ);
    cudaFuncSetAttribute(attn_fused, cudaFuncAttributeMaxDynamicSharedMemorySize, FS_TOT);

    int n4per = 3 * DD * DD / 4;
    int n1 = 3 * DFFX * DD / 4;
    int nM = BT * DD / 4;
    cvt_qkv<<<dim3((n4per + 255) / 256, 3), 256>>>(Wq, Wk, Wv, wqkv, n4per);
    {
        CvtSeg s0{Wp, wph, n4per}, s1{Wo, woh, n4per}, s2{W1, w1h, n1}, s3{MSK, mkh, nM};
        int maxb = (nM + 255) / 256;
        cvt_misc<<<dim3(maxb, 4), 256>>>(s0, s1, s2, s3);
    }
    int n2 = 3 * 3 * DD * DFFX;
    cvt_w2<<<(n2 + 255) / 256, 256>>>(W2, w2h);

    dim3 gP(4, MP / 128);
    dim3 gP3(4, MP / 128, 3);
    dim3 gQKV(12, MP / 128);
    dim3 gF(8, MP / 128);
    dim3 gAt(8, ZZ);

    // hoisted: P = MSK @ Wp[l]^T for all 3 layers
    hmma_gemm<1, false, false, 3><<<gP3, 256, SMEMSZ>>>(
        mkh, wph, nullptr, nullptr, nullptr, nullptr, nullptr,
        nullptr, pph, nullptr, nullptr, nullptr, BT, DD, DD,
        (long)DD * DD, (long)ZT64);

    for (int i = 0; i < 3; i++) {
        size_t oD = (size_t)i * DD;
        addln_kernel<true><<<BT, 128>>>(i == 0 ? X0 : x, x, PE + (size_t)i * TT * DD,
                                        l1a + oD, l1b + oD, nullptr, xnh);
        hmma_gemm<1, false, false, 5><<<gQKV, 256, SMEMSZ>>>(
            xnh, wqkv + (size_t)i * 3 * DD * DD,
            bq + oD, Ub + oD, Vb + oD, bk + oD, bv + oD,
            nullptr, quh, qvh, kkh, vth, BT, 3 * DD, DD, 0, 0);
        attn_fused<<<gAt, 256, FS_TOT>>>(quh, qvh, kkh, pph + (size_t)i * ZT64, vth, cxh);
        hmma_gemm<1, true, false, 0><<<gP, 256, SMEMSZ>>>(
            cxh, woh + (size_t)i * DD * DD, bo + oD, nullptr, nullptr, nullptr, nullptr,
            x, nullptr, nullptr, nullptr, nullptr, BT, DD, DD, 0, 0);
        addln_kernel<true><<<BT, 128>>>(x, nullptr, nullptr,
                                        l2a + oD, l2b + oD, nullptr, xnh);
        hmma_gemm<1, false, true, 1><<<gF, 256, SMEMSZ>>>(
            xnh, w1h + (size_t)i * DFFX * DD,
            b1 + (size_t)i * DFFX, nullptr, nullptr, nullptr, nullptr,
            nullptr, hph, nullptr, nullptr, nullptr, BT, DFFX, DD, 0, 0);
        hmma_gemm<3, true, false, 0><<<gP, 256, SMEMSZ>>>(
            hph, w2h + (size_t)i * 3 * DD * DFFX,
            b2 + oD, nullptr, nullptr, nullptr, nullptr,
            x, nullptr, nullptr, nullptr, nullptr, BT, DD, DFFX, 0, 0);
    }
    addln_kernel<false><<<BT, 128>>>(x, nullptr, nullptr, fna, fnb, x, nullptr);
}

// round 15
// speedup vs baseline: 1.0059x; 1.0059x over previous
#include <cuda_runtime.h>
#include <cuda_fp16.h>
#include <math.h>
#include <stdint.h>

#define BB   64
#define TT   351
#define DD   512
#define HH   8
#define DFFX 1024
#define BT   (BB*TT)       // 22464
#define MP   22528
#define HPR  22784
#define TP   384
#define ZZ   (BB*HH)       // 512
#define ZT64 ((size_t)ZZ*TP*64)
#define STAGE_BYTES 36864
#define SMEMSZ (3*STAGE_BYTES)

// fused-attention smem layout (bytes), q-block = 48 rows
#define FS_PITCH 392
#define AT_QU 75264
#define AT_QV 84480
#define AT_B0 93696
#define AT_B1 102912
#define AF_A  75264
#define AF_PITCH 784
#define FS_TOT 112896             // occ 2

// ---------------- scratch ------------------------------------------------------------
static __device__ __half g_quh[ZT64];
static __device__ __half g_qvh[ZT64];
static __device__ __half g_kkh[ZT64];
static __device__ __half g_pph[3*ZT64];
static __device__ __half g_vth[ZT64];
static __device__ __half g_xnh[MP*(size_t)DD];
static __device__ __half g_mkh[MP*(size_t)DD];
static __device__ __half g_cxh[MP*(size_t)DD];
static __device__ __half g_hph[(size_t)HPR*DFFX];
static __device__ __half g_wqkv[3*3*DD*DD];
static __device__ __half g_wph[3*DD*DD], g_woh[3*DD*DD];
static __device__ __half g_w1h[3*DFFX*DD];
static __device__ __half g_w2h[3*3*DD*DFFX];

// ---------------- PTX helpers --------------------------------------------------------
__device__ __forceinline__ uint32_t smem_u32(const void* p) {
    uint32_t a;
    asm("{ .reg .u64 t; cvta.to.shared.u64 t, %1; cvt.u32.u64 %0, t; }" : "=r"(a) : "l"(p));
    return a;
}
__device__ __forceinline__ void cp16(uint32_t dst, const void* src) {
    asm volatile("cp.async.cg.shared.global [%0], [%1], 16;" :: "r"(dst), "l"(src) : "memory");
}
#define CP_COMMIT() asm volatile("cp.async.commit_group;" ::: "memory")
#define CP_WAIT1()  asm volatile("cp.async.wait_group 1;" ::: "memory")
#define CP_WAIT0()  asm volatile("cp.async.wait_group 0;" ::: "memory")

__device__ __forceinline__ void mma16816(float* c, const uint32_t* a, const uint32_t* b) {
    asm volatile(
        "mma.sync.aligned.m16n8k16.row.col.f32.f16.f16.f32 "
        "{%0,%1,%2,%3}, {%4,%5,%6,%7}, {%8,%9}, {%0,%1,%2,%3};"
        : "+f"(c[0]), "+f"(c[1]), "+f"(c[2]), "+f"(c[3])
        : "r"(a[0]), "r"(a[1]), "r"(a[2]), "r"(a[3]), "r"(b[0]), "r"(b[1]));
}
__device__ __forceinline__ void ldsm4(uint32_t* r, uint32_t addr) {
    asm volatile("ldmatrix.sync.aligned.m8n8.x4.shared.b16 {%0,%1,%2,%3}, [%4];"
        : "=r"(r[0]), "=r"(r[1]), "=r"(r[2]), "=r"(r[3]) : "r"(addr));
}
__device__ __forceinline__ uint32_t packh(float a, float b) {
    __half2 h = __floats2half2_rn(a, b);
    return *reinterpret_cast<uint32_t*>(&h);
}

// ---------------- conversion kernels -------------------------------------------------
__global__ void cvt_qkv(const float* __restrict__ Wq, const float* __restrict__ Wk,
                        const float* __restrict__ Wv, __half* __restrict__ dst, int n4per) {
    int i = blockIdx.x * 256 + threadIdx.x;
    if (i >= n4per) return;
    int tsel = blockIdx.y;
    const float* s = (tsel == 0) ? Wq : (tsel == 1) ? Wk : Wv;
    float4 v = ((const float4*)s)[i];
    const int per_l4 = DD * DD / 4;
    int l = i / per_l4, r = i - l * per_l4;
    long di = (long)l * (3 * per_l4) + (long)tsel * per_l4 + r;
    uint2 st; st.x = packh(v.x, v.y); st.y = packh(v.z, v.w);
    ((uint2*)dst)[di] = st;
}
struct CvtSeg { const float* src; __half* dst; int n4; };
__global__ void cvt_misc(CvtSeg s0, CvtSeg s1, CvtSeg s2, CvtSeg s3) {
    CvtSeg s = (blockIdx.y == 0) ? s0 : (blockIdx.y == 1) ? s1 : (blockIdx.y == 2) ? s2 : s3;
    int i = blockIdx.x * 256 + threadIdx.x;
    if (i >= s.n4) return;
    float4 v = ((const float4*)s.src)[i];
    uint2 st; st.x = packh(v.x, v.y); st.y = packh(v.z, v.w);
    ((uint2*)s.dst)[i] = st;
}
// W2 in: [l][n][k][s] -> out [l][s][n][k]
__global__ void cvt_w2(const float* __restrict__ in, __half* __restrict__ hi) {
    int idx = blockIdx.x * 256 + threadIdx.x;
    const int per_l = 3 * DD * DFFX;
    if (idx >= 3 * per_l) return;
    int l = idx / per_l; int r = idx - l * per_l;
    int s = r / (DD * DFFX); int r2 = r - s * (DD * DFFX);
    int n = r2 / DFFX; int k2 = r2 - n * DFFX;
    hi[idx] = __float2half_rn(in[(((size_t)l * DD + n) * DFFX + k2) * 3 + s]);
}

// ---------------- HMMA 1-term fp16 GEMM, K-chunk 64, single barrier per chunk --------
// MODE 0: fp32 C (+ACC). MODE 1: fp16 padded-H remap (FF1). MODE 3: head-major
//         (gridDim.z layer batching). MODE 5: merged QKV epilogue.
template<int TAPS, bool ACC, bool RELU, int MODE>
__global__ __launch_bounds__(256, 2)
void hmma_gemm(const __half* __restrict__ Ahi, const __half* __restrict__ Bhi,
               const float* __restrict__ bias, const float* __restrict__ bias2,
               const float* __restrict__ bias3, const float* __restrict__ bias4,
               const float* __restrict__ bias5,
               float* __restrict__ Cf,
               __half* __restrict__ O1h, __half* __restrict__ O2h,
               __half* __restrict__ O3h, __half* __restrict__ O4h,
               int Mstore, int N, int K, long lws, long los) {
    extern __shared__ char sm[];
    uint32_t dbase = smem_u32(sm);
    Bhi += (long)blockIdx.z * lws;
    O1h += (long)blockIdx.z * los;
    int tid = threadIdx.x, lane = tid & 31, w = tid >> 5;
    int wm = (w & 1) << 6, wn = (w >> 1) << 5;
    int bm = blockIdx.y << 7, bn = blockIdx.x << 7;

    uint32_t so[4]; long ga[4], gb[4];
#pragma unroll
    for (int j = 0; j < 4; j++) {
        int idx = tid + 256 * j; int row = idx >> 3, c16 = idx & 7;
        so[j] = row * 144 + c16 * 16;
        int grow = bm + row;
        long arow;
        if (TAPS == 3) { int b = grow / 351; int t = grow - b * 351; arow = (long)b * 353 + t; }
        else arow = grow;
        ga[j] = arow * (long)K + c16 * 8;
        gb[j] = (long)(bn + row) * K + c16 * 8;
    }
    const int kch = K >> 6;
    const int nch = TAPS * kch;

#define LOAD_CHUNK(c, stg) do { \
        int s_ = (c) / kch; int kb_ = ((c) - s_ * kch) << 6; \
        long sK_ = (TAPS == 3) ? (long)s_ * K : 0; \
        long sNK_ = (TAPS == 3) ? (long)s_ * N * K : 0; \
        uint32_t sb_ = dbase + (stg) * STAGE_BYTES; \
        _Pragma("unroll") \
        for (int j = 0; j < 4; j++) { \
            cp16(sb_ + so[j],         Ahi + sK_ + ga[j] + kb_); \
            cp16(sb_ + 18432 + so[j], Bhi + sNK_ + gb[j] + kb_); \
        } \
    } while (0)

    float acc[4][4][4];
#pragma unroll
    for (int a = 0; a < 4; a++)
#pragma unroll
        for (int b = 0; b < 4; b++)
#pragma unroll
            for (int q2 = 0; q2 < 4; q2++) acc[a][b][q2] = 0.0f;

    int bq = lane & 3, bg = lane >> 2;
    uint32_t aoff = (uint32_t)(wm + (lane & 15)) * 144 + (uint32_t)(((lane >> 4) & 1) << 4);
    uint32_t boff = 18432u + (uint32_t)(wn + ((lane >> 4) << 3) + (lane & 7)) * 144
                  + (uint32_t)(((lane >> 3) & 1) << 4);

    // prologue: chunks 0,1 (groups 0,1)
    LOAD_CHUNK(0, 0);
    CP_COMMIT();
    LOAD_CHUNK(1, 1);
    CP_COMMIT();
#pragma unroll 1
    for (int c = 0; c < nch; c++) {
        // chunk c is group #c; groups committed = c+2 -> WAIT1 guarantees group c done
        CP_WAIT1();
        __syncthreads();          // also orders compute(c-1) before overwriting its stage
        if (c + 2 < nch) LOAD_CHUNK(c + 2, (c + 2) % 3);
        CP_COMMIT();              // unconditional: keeps group numbering exact
        uint32_t sb = dbase + (c % 3) * STAGE_BYTES;
#pragma unroll
        for (int k16 = 0; k16 < 4; k16++) {
            uint32_t kof = k16 * 32;
            uint32_t bh[4][2], t[4];
            ldsm4(t, sb + boff + kof);
            bh[0][0] = t[0]; bh[0][1] = t[1]; bh[1][0] = t[2]; bh[1][1] = t[3];
            ldsm4(t, sb + boff + 2304 + kof);
            bh[2][0] = t[0]; bh[2][1] = t[1]; bh[3][0] = t[2]; bh[3][1] = t[3];
#pragma unroll
            for (int mi = 0; mi < 4; mi++) {
                uint32_t ah[4];
                ldsm4(ah, sb + aoff + mi * 2304 + kof);
#pragma unroll
                for (int ni = 0; ni < 4; ni++)
                    mma16816(acc[mi][ni], ah, bh[ni]);
            }
        }
    }
#undef LOAD_CHUNK

#pragma unroll
    for (int mi = 0; mi < 4; mi++) {
#pragma unroll
        for (int half = 0; half < 2; half++) {
            int m = bm + wm + mi * 16 + bg + half * 8;
            if (m >= Mstore) continue;
            int b = 0, t = 0; long crow = m;
            if (MODE == 1) { b = m / 351; t = m - b * 351; crow = (long)b * 353 + 1 + t; }
            if (MODE >= 2) { b = m / 351; t = m - b * 351; }
#pragma unroll
            for (int ni = 0; ni < 4; ni++) {
                int col = bn + wn + ni * 8 + bq * 2;
                float v0 = acc[mi][ni][half * 2 + 0];
                float v1 = acc[mi][ni][half * 2 + 1];
                if (MODE == 0 || MODE == 1 || MODE == 3) {
                    if (bias) { v0 += bias[col]; v1 += bias[col + 1]; }
                }
                if (RELU) { v0 = fmaxf(v0, 0.0f); v1 = fmaxf(v1, 0.0f); }
                if (MODE == 0) {
                    float* cp = Cf + (long)m * N + col;
                    if (ACC) { v0 += cp[0]; v1 += cp[1]; }
                    float2 st; st.x = v0; st.y = v1;
                    *(float2*)cp = st;
                } else if (MODE == 1) {
                    *(uint32_t*)(O1h + crow * (long)N + col) = packh(v0, v1);
                } else if (MODE == 3) {
                    int h = col >> 6, d = col & 63;
                    long base = ((long)(b * 8 + h) * TP + t) * 64 + d;
                    *(uint32_t*)(O1h + base) = packh(v0, v1);
                } else if (MODE == 5) {
                    int seg = col >> 9, cs = col & 511;
                    int h = cs >> 6, d = cs & 63;
                    if (seg == 0) {
                        long base = ((long)(b * 8 + h) * TP + t) * 64 + d;
                        float q0v = v0 + bias[cs], q1v = v1 + bias[cs + 1];
                        *(uint32_t*)(O1h + base) = packh(q0v + bias2[cs], q1v + bias2[cs + 1]);
                        *(uint32_t*)(O2h + base) = packh(q0v + bias3[cs], q1v + bias3[cs + 1]);
                    } else if (seg == 1) {
                        long base = ((long)(b * 8 + h) * TP + t) * 64 + d;
                        *(uint32_t*)(O3h + base) = packh(v0 + bias4[cs], v1 + bias4[cs + 1]);
                    } else {
                        float u0 = v0 + bias5[cs], u1 = v1 + bias5[cs + 1];
                        O4h[((long)(b * 8 + h) * 64 + d) * TP + t]     = __float2half_rn(u0);
                        O4h[((long)(b * 8 + h) * 64 + d + 1) * TP + t] = __float2half_rn(u1);
                    }
                }
            }
        }
    }
}

// ---------------- fully fused attention (single barrier per chunk) -------------------
__global__ __launch_bounds__(256, 2)
void attn_fused(const __half* __restrict__ quh, const __half* __restrict__ qvh,
                const __half* __restrict__ kkh, const __half* __restrict__ pph,
                const __half* __restrict__ vth, __half* __restrict__ Ch) {
    extern __shared__ char sm[];
    uint32_t dbase = smem_u32(sm);
    float* S = (float*)sm;
    int z = blockIdx.y, q0 = blockIdx.x * 48;
    int tid = threadIdx.x, lane = tid & 31, w = tid >> 5;
    int cb = w << 3;
    int bq = lane & 3, bg = lane >> 2;

    for (int i = tid; i < 512; i += 256) {
        int r = i >> 3, c = i & 7;
        int gq = q0 + r; if (gq >= TP) gq = q0;
        cp16(dbase + AT_QU + r * 144 + c * 16, quh + ((long)z * TP + gq) * 64 + c * 8);
        cp16(dbase + AT_QV + r * 144 + c * 16, qvh + ((long)z * TP + gq) * 64 + c * 8);
        cp16(dbase + AT_B0 + r * 144 + c * 16, kkh + ((long)z * TP + r) * 64 + c * 8);
    }
    CP_COMMIT();
    CP_WAIT0();
    __syncthreads();

    uint32_t afr[4][4][4];
#pragma unroll
    for (int mi = 0; mi < 3; mi++)
#pragma unroll
        for (int k16 = 0; k16 < 4; k16++) {
            const char* pa = sm + AT_QU + (mi * 16 + bg) * 144 + k16 * 32 + bq * 4;
            afr[mi][k16][0] = *(const uint32_t*)pa;
            afr[mi][k16][1] = *(const uint32_t*)(pa + 8 * 144);
            afr[mi][k16][2] = *(const uint32_t*)(pa + 16);
            afr[mi][k16][3] = *(const uint32_t*)(pa + 8 * 144 + 16);
        }

#pragma unroll 1
    for (int ch = 0; ch < 12; ch++) {
        CP_WAIT0();               // all committed groups done -> chunk ch data ready
        __syncthreads();          // orders compute(ch-1) before buffer reuse
        if (ch + 1 < 12) {
            const __half* src = (ch + 1 < 6) ? kkh : pph;
            int rows0 = ((ch + 1) % 6) * 64;
            uint32_t bb = ((ch + 1) & 1) ? AT_B1 : AT_B0;
            for (int i = tid; i < 512; i += 256) {
                int r = i >> 3, c = i & 7;
                cp16(dbase + bb + r * 144 + c * 16,
                     src + ((long)z * TP + rows0 + r) * 64 + c * 8);
            }
        }
        CP_COMMIT();
        if (ch == 6) {
#pragma unroll
            for (int mi = 0; mi < 4; mi++)
#pragma unroll
                for (int k16 = 0; k16 < 4; k16++) {
                    const char* pa = sm + AT_QV + (mi * 16 + bg) * 144 + k16 * 32 + bq * 4;
                    afr[mi][k16][0] = *(const uint32_t*)pa;
                    afr[mi][k16][1] = *(const uint32_t*)(pa + 8 * 144);
                    afr[mi][k16][2] = *(const uint32_t*)(pa + 16);
                    afr[mi][k16][3] = *(const uint32_t*)(pa + 8 * 144 + 16);
                }
        }
        uint32_t bb = (ch & 1) ? AT_B1 : AT_B0;
        int col0 = (ch % 6) * 64;
        if (ch < 6) {
            float acc[3][4];
#pragma unroll
            for (int a = 0; a < 3; a++)
#pragma unroll
                for (int e = 0; e < 4; e++) acc[a][e] = 0.0f;
#pragma unroll
            for (int k16 = 0; k16 < 4; k16++) {
                const char* pb = sm + bb + (cb + bg) * 144 + k16 * 32 + bq * 4;
                uint32_t bh[2];
                bh[0] = *(const uint32_t*)pb;
                bh[1] = *(const uint32_t*)(pb + 16);
#pragma unroll
                for (int mi = 0; mi < 3; mi++)
                    mma16816(acc[mi], afr[mi][k16], bh);
            }
#pragma unroll
            for (int mi = 0; mi < 3; mi++)
#pragma unroll
                for (int half = 0; half < 2; half++) {
                    int r = mi * 16 + bg + half * 8;
                    int col = col0 + cb + bq * 2;
                    S[r * FS_PITCH + col]     = acc[mi][half * 2 + 0];
                    S[r * FS_PITCH + col + 1] = acc[mi][half * 2 + 1];
                }
        } else {
            float acc[4][4];
#pragma unroll
            for (int a = 0; a < 4; a++)
#pragma unroll
                for (int e = 0; e < 4; e++) acc[a][e] = 0.0f;
#pragma unroll
            for (int k16 = 0; k16 < 4; k16++) {
                const char* pb = sm + bb + (cb + bg) * 144 + k16 * 32 + bq * 4;
                uint32_t bh[2];
                bh[0] = *(const uint32_t*)pb;
                bh[1] = *(const uint32_t*)(pb + 16);
#pragma unroll
                for (int mi = 0; mi < 4; mi++)
                    mma16816(acc[mi], afr[mi][k16], bh);
            }
#pragma unroll
            for (int mi = 0; mi < 4; mi++)
#pragma unroll
                for (int half = 0; half < 2; half++) {
                    int r = mi * 16 + bg + half * 8;
                    if (r > 48) continue;
                    int rp = q0 + r;
#pragma unroll
                    for (int e = 0; e < 2; e++) {
                        int jj = col0 + cb + bq * 2 + e;
                        if (jj >= TT) continue;
                        float v = acc[mi][half * 2 + e];
                        if (jj >= 350 - rp) {
                            if (r < 48) S[r * FS_PITCH + jj - 350 + rp] += v;
                        } else if (r >= 1) {
                            S[(r - 1) * FS_PITCH + jj + rp + 1] += v;
                        }
                    }
                }
        }
    }
    __syncthreads();   // S complete before softmax

    // ---- softmax via ex2.approx.f16x2 -> fp16 A tile (fully convergent) ----
    if (tid < 192) {
        int r = tid >> 2, qu = tid & 3;
        const float scale = 0.044194173824159216f;
        const float a_l2 = scale * 1.4426950408889634f;
        float* Srow = S + r * FS_PITCH;
        char* Arow = sm + AF_A + r * AF_PITCH;
        int c0 = qu * 96;
        float mx = -1e30f;
        for (int cc = c0; cc < c0 + 96; cc++)
            if (cc < TT) mx = fmaxf(mx, Srow[cc]);
        mx = fmaxf(mx, __shfl_xor_sync(0xffffffffu, mx, 1));
        mx = fmaxf(mx, __shfl_xor_sync(0xffffffffu, mx, 2));
        float boff2 = -mx * a_l2;
        float sum = 0.0f;
        for (int cc = c0; cc < c0 + 96; cc += 2) {
            float x0 = (cc < TT)     ? Srow[cc]     * a_l2 + boff2 : -60.0f;
            float x1 = (cc + 1 < TT) ? Srow[cc + 1] * a_l2 + boff2 : -60.0f;
            __half2 hx = __floats2half2_rn(x0, x1);
            __half2 he = h2exp2(hx);
            float2 fe = __half22float2(he);
            sum += fe.x + fe.y;
            *(__half2*)(Arow + cc * 2) = he;
        }
        sum += __shfl_xor_sync(0xffffffffu, sum, 1);
        sum += __shfl_xor_sync(0xffffffffu, sum, 2);
        __half2 inv2 = __half2half2(__float2half_rn(1.0f / sum));
        for (int cc = c0; cc < c0 + 96; cc += 2) {
            __half2 v = *(__half2*)(Arow + cc * 2);
            *(__half2*)(Arow + cc * 2) = __hmul2(v, inv2);
        }
    }
    __syncthreads();

    // ---- load V tile over dead score region ----
    for (int i = tid; i < 3072; i += 256) {
        int d = i / 48, c16 = i - d * 48;
        cp16(dbase + d * AF_PITCH + c16 * 16,
             vth + ((long)z * 64 + d) * TP + c16 * 8);
    }
    CP_COMMIT(); CP_WAIT0(); __syncthreads();

    // ---- ctx GEMM: out[48 x 64] = A[48 x 384] @ V^T, 6 warps, ldsm fragments ----
    if (w < 6) {
        int wr = w % 3, wc = w / 3;
        uint32_t aoffc = smem_u32(sm) + AF_A
                       + (uint32_t)(wr * 16 + (lane & 15)) * AF_PITCH
                       + (uint32_t)(((lane >> 4) & 1) << 4);
        uint32_t boffc = smem_u32(sm)
                       + (uint32_t)(wc * 32 + ((lane >> 4) << 3) + (lane & 7)) * AF_PITCH
                       + (uint32_t)(((lane >> 3) & 1) << 4);
        float acc[4][4];
#pragma unroll
        for (int a = 0; a < 4; a++)
#pragma unroll
            for (int e = 0; e < 4; e++) acc[a][e] = 0.0f;
#pragma unroll 1
        for (int k16 = 0; k16 < 24; k16++) {
            uint32_t kof = k16 * 32;
            uint32_t ah[4], t[4], bh[4][2];
            ldsm4(ah, aoffc + kof);
            ldsm4(t, boffc + kof);
            bh[0][0] = t[0]; bh[0][1] = t[1]; bh[1][0] = t[2]; bh[1][1] = t[3];
            ldsm4(t, boffc + 16 * AF_PITCH + kof);
            bh[2][0] = t[0]; bh[2][1] = t[1]; bh[3][0] = t[2]; bh[3][1] = t[3];
#pragma unroll
            for (int ni = 0; ni < 4; ni++)
                mma16816(acc[ni], ah, bh[ni]);
        }
        int b = z >> 3, h = z & 7;
#pragma unroll
        for (int half = 0; half < 2; half++) {
            int gq = q0 + wr * 16 + bg + half * 8;
            if (gq >= TT) continue;
#pragma unroll
            for (int ni = 0; ni < 4; ni++) {
                int col = wc * 32 + ni * 8 + bq * 2;
                long addr = ((long)(b * 351 + gq)) * DD + h * 64 + col;
                *(uint32_t*)(Ch + addr) = packh(acc[ni][half * 2], acc[ni][half * 2 + 1]);
            }
        }
    }
}

// ---------------- add pos-emb + LayerNorm (float4-vectorized) ------------------------
template<bool F16O>
__global__ void addln_kernel(const float* __restrict__ xin, float* __restrict__ xupd,
                             const float* __restrict__ pe,
                             const float* __restrict__ ga, const float* __restrict__ gb,
                             float* __restrict__ out, __half* __restrict__ ohi) {
    int row = blockIdx.x;
    int t   = row % TT;
    int tid = threadIdx.x;
    int c4 = tid << 2;
    float4 v4 = *(const float4*)(xin + (size_t)row * DD + c4);
    if (pe) {
        float4 p4 = *(const float4*)(pe + (size_t)t * DD + c4);
        v4.x += p4.x; v4.y += p4.y; v4.z += p4.z; v4.w += p4.w;
        *(float4*)(xupd + (size_t)row * DD + c4) = v4;
    }
    __shared__ float sh[4];
    float s = v4.x + v4.y + v4.z + v4.w;
#pragma unroll
    for (int o = 16; o > 0; o >>= 1) s += __shfl_xor_sync(0xffffffffu, s, o);
    if ((tid & 31) == 0) sh[tid >> 5] = s;
    __syncthreads();
    float mean = (sh[0] + sh[1] + sh[2] + sh[3]) * (1.0f / DD);
    __syncthreads();
    float d0 = v4.x - mean, d1 = v4.y - mean, d2 = v4.z - mean, d3 = v4.w - mean;
    float sq = d0 * d0 + d1 * d1 + d2 * d2 + d3 * d3;
#pragma unroll
    for (int o = 16; o > 0; o >>= 1) sq += __shfl_xor_sync(0xffffffffu, sq, o);
    if ((tid & 31) == 0) sh[tid >> 5] = sq;
    __syncthreads();
    float var  = sh[0] + sh[1] + sh[2] + sh[3];
    float stdv = sqrtf(var * (1.0f / (DD - 1)));
    float inv  = 1.0f / (stdv + 1e-6f);
    float4 a4 = *(const float4*)(ga + c4);
    float4 b4 = *(const float4*)(gb + c4);
    float o0 = a4.x * d0 * inv + b4.x;
    float o1 = a4.y * d1 * inv + b4.y;
    float o2 = a4.z * d2 * inv + b4.z;
    float o3 = a4.w * d3 * inv + b4.w;
    if (F16O) {
        uint2 st; st.x = packh(o0, o1); st.y = packh(o2, o3);
        *(uint2*)(ohi + (size_t)row * DD + c4) = st;
    } else {
        float4 st; st.x = o0; st.y = o1; st.z = o2; st.w = o3;
        *(float4*)(out + (size_t)row * DD + c4) = st;
    }
}

// ------------------------------------ launch -----------------------------------------
extern "C" void kernel_launch(void* const* d_in, const int* in_sizes, int n_in,
                              void* d_out, int out_size) {
    const float* X0  = (const float*)d_in[0];
    const float* MSK = (const float*)d_in[1];
    const float* PE  = (const float*)d_in[2];
    const float* Wq  = (const float*)d_in[3];
    const float* bq  = (const float*)d_in[4];
    const float* Wk  = (const float*)d_in[5];
    const float* bk  = (const float*)d_in[6];
    const float* Wv  = (const float*)d_in[7];
    const float* bv  = (const float*)d_in[8];
    const float* Wp  = (const float*)d_in[9];
    const float* Ub  = (const float*)d_in[10];
    const float* Vb  = (const float*)d_in[11];
    const float* Wo  = (const float*)d_in[12];
    const float* bo  = (const float*)d_in[13];
    const float* l1a = (const float*)d_in[14];
    const float* l1b = (const float*)d_in[15];
    const float* l2a = (const float*)d_in[16];
    const float* l2b = (const float*)d_in[17];
    const float* W1  = (const float*)d_in[18];
    const float* b1  = (const float*)d_in[19];
    const float* W2  = (const float*)d_in[20];
    const float* b2  = (const float*)d_in[21];
    const float* fna = (const float*)d_in[22];
    const float* fnb = (const float*)d_in[23];
    float* x = (float*)d_out;

    __half *quh, *qvh, *kkh, *pph, *vth;
    __half *xnh, *mkh, *cxh, *hph;
    __half *wqkv, *wph, *woh, *w1h, *w2h;
    cudaGetSymbolAddress((void**)&quh, g_quh); cudaGetSymbolAddress((void**)&qvh, g_qvh);
    cudaGetSymbolAddress((void**)&kkh, g_kkh); cudaGetSymbolAddress((void**)&pph, g_pph);
    cudaGetSymbolAddress((void**)&vth, g_vth);
    cudaGetSymbolAddress((void**)&xnh, g_xnh); cudaGetSymbolAddress((void**)&mkh, g_mkh);
    cudaGetSymbolAddress((void**)&cxh, g_cxh); cudaGetSymbolAddress((void**)&hph, g_hph);
    cudaGetSymbolAddress((void**)&wqkv, g_wqkv);
    cudaGetSymbolAddress((void**)&wph, g_wph); cudaGetSymbolAddress((void**)&woh, g_woh);
    cudaGetSymbolAddress((void**)&w1h, g_w1h); cudaGetSymbolAddress((void**)&w2h, g_w2h);

    cudaFuncSetAttribute(hmma_gemm<1, true,  false, 0>, cudaFuncAttributeMaxDynamicSharedMemorySize, SMEMSZ);
    cudaFuncSetAttribute(hmma_gemm<3, true,  false, 0>, cudaFuncAttributeMaxDynamicSharedMemorySize, SMEMSZ);
    cudaFuncSetAttribute(hmma_gemm<1, false, true,  1>, cudaFuncAttributeMaxDynamicSharedMemorySize, SMEMSZ);
    cudaFuncSetAttribute(hmma_gemm<1, false, false, 3>, cudaFuncAttributeMaxDynamicSharedMemorySize, SMEMSZ);
    cudaFuncSetAttribute(hmma_gemm<1, false, false, 5>, cudaFuncAttributeMaxDynamicSharedMemorySize, SMEMSZ);
    cudaFuncSetAttribute(attn_fused, cudaFuncAttributeMaxDynamicSharedMemorySize, FS_TOT);

    int n4per = 3 * DD * DD / 4;
    int n1 = 3 * DFFX * DD / 4;
    int nM = BT * DD / 4;
    cvt_qkv<<<dim3((n4per + 255) / 256, 3), 256>>>(Wq, Wk, Wv, wqkv, n4per);
    {
        CvtSeg s0{Wp, wph, n4per}, s1{Wo, woh, n4per}, s2{W1, w1h, n1}, s3{MSK, mkh, nM};
        int maxb = (nM + 255) / 256;
        cvt_misc<<<dim3(maxb, 4), 256>>>(s0, s1, s2, s3);
    }
    int n2 = 3 * 3 * DD * DFFX;
    cvt_w2<<<(n2 + 255) / 256, 256>>>(W2, w2h);

    dim3 gP(4, MP / 128);
    dim3 gP3(4, MP / 128, 3);
    dim3 gQKV(12, MP / 128);
    dim3 gF(8, MP / 128);
    dim3 gAt(8, ZZ);

    // hoisted: P = MSK @ Wp[l]^T for all 3 layers
    hmma_gemm<1, false, false, 3><<<gP3, 256, SMEMSZ>>>(
        mkh, wph, nullptr, nullptr, nullptr, nullptr, nullptr,
        nullptr, pph, nullptr, nullptr, nullptr, BT, DD, DD,
        (long)DD * DD, (long)ZT64);

    for (int i = 0; i < 3; i++) {
        size_t oD = (size_t)i * DD;
        addln_kernel<true><<<BT, 128>>>(i == 0 ? X0 : x, x, PE + (size_t)i * TT * DD,
                                        l1a + oD, l1b + oD, nullptr, xnh);
        hmma_gemm<1, false, false, 5><<<gQKV, 256, SMEMSZ>>>(
            xnh, wqkv + (size_t)i * 3 * DD * DD,
            bq + oD, Ub + oD, Vb + oD, bk + oD, bv + oD,
            nullptr, quh, qvh, kkh, vth, BT, 3 * DD, DD, 0, 0);
        attn_fused<<<gAt, 256, FS_TOT>>>(quh, qvh, kkh, pph + (size_t)i * ZT64, vth, cxh);
        hmma_gemm<1, true, false, 0><<<gP, 256, SMEMSZ>>>(
            cxh, woh + (size_t)i * DD * DD, bo + oD, nullptr, nullptr, nullptr, nullptr,
            x, nullptr, nullptr, nullptr, nullptr, BT, DD, DD, 0, 0);
        addln_kernel<true><<<BT, 128>>>(x, nullptr, nullptr,
                                        l2a + oD, l2b + oD, nullptr, xnh);
        hmma_gemm<1, false, true, 1><<<gF, 256, SMEMSZ>>>(
            xnh, w1h + (size_t)i * DFFX * DD,
            b1 + (size_t)i * DFFX, nullptr, nullptr, nullptr, nullptr,
            nullptr, hph, nullptr, nullptr, nullptr, BT, DFFX, DD, 0, 0);
        hmma_gemm<3, true, false, 0><<<gP, 256, SMEMSZ>>>(
            hph, w2h + (size_t)i * 3 * DD * DFFX,
            b2 + oD, nullptr, nullptr, nullptr, nullptr,
            x, nullptr, nullptr, nullptr, nullptr, BT, DD, DFFX, 0, 0);
    }
    addln_kernel<false><<<BT, 128>>>(x, nullptr, nullptr, fna, fnb, x, nullptr);
}